// round 10
// baseline (speedup 1.0000x reference)
#include <cuda_runtime.h>
#include <cuda_fp16.h>

#define N_NODES 10000
#define N_EDGES 640000
#define D 128
#define N_LAYERS 4
#define CAP 192            // max in-degree bucket (deg ~ Binom(640k,1e-4): mean 64, sd 8 -> 16 sigma margin)

#define H_SCALE   0.015625f   // 2^-6 applied when storing fp16 messages (exact)
#define H_UNSCALE 64.0f       // 2^6 applied when folding chunk sums into fp32

// Scratch (static __device__ — no allocations allowed; zero-initialized at load)
__device__ float  g_bufA[N_NODES * D];       // layer input (post-relu, fp32)
__device__ float  g_bufB[N_NODES * D];       // hl = X@W + b (fp32, self-loop + precision)
__device__ __half g_bufH[N_NODES * D];       // hl * 2^-6 in fp16 (gather operand)
__device__ int    g_cursor[N_NODES];         // per-node degree counter (left at 0 by every launch)
__device__ int    g_ell[N_NODES * CAP];      // padded per-dst source lists

// ---------------------------------------------------------------------------
// GEMM: Y = X @ W + b using packed dual-fp32 FMA (fma.rn.f32x2).
// Layer 0 variant is fused with the ELL fill (block-range split).
// ---------------------------------------------------------------------------
#define GR 32
#define RPAD (GR + 2)
#define GEMM_GRID ((N_NODES + GR - 1) / GR)          // 313
#define FILL_GRID ((N_EDGES / 8 + 255) / 256)        // 313

__device__ __forceinline__ float2 ffma2(float2 a, float2 b, float2 c) {
    unsigned long long ua = *reinterpret_cast<unsigned long long*>(&a);
    unsigned long long ub = *reinterpret_cast<unsigned long long*>(&b);
    unsigned long long uc = *reinterpret_cast<unsigned long long*>(&c);
    unsigned long long r;
    asm("fma.rn.f32x2 %0, %1, %2, %3;" : "=l"(r) : "l"(ua), "l"(ub), "l"(uc));
    return *reinterpret_cast<float2*>(&r);
}

// GEMM body: 32 rows x 128 cols per block, 128 active threads.
__device__ __forceinline__ void gemm_body(
    int blk, const float* __restrict__ X,
    const float* __restrict__ W, const float* __restrict__ B,
    float* sxt /*[D][RPAD]*/, float* sw_s /*[32][D]*/) {

    int tid = threadIdx.x;                 // 0..127
    int cg = tid & 31, rg = tid >> 5;
    int c0 = cg * 4;
    int row0 = blk * GR;

    #pragma unroll 4
    for (int r = 0; r < GR; r++) {
        int gr = row0 + r;
        sxt[tid * RPAD + r] = (gr < N_NODES) ? X[gr * D + tid] : 0.0f;
    }

    float4 bias = *(const float4*)&B[c0];
    float2 acc[4][4];
    #pragma unroll
    for (int p = 0; p < 4; p++) {
        acc[p][0] = make_float2(bias.x, bias.x);
        acc[p][1] = make_float2(bias.y, bias.y);
        acc[p][2] = make_float2(bias.z, bias.z);
        acc[p][3] = make_float2(bias.w, bias.w);
    }

    for (int kc = 0; kc < D; kc += 32) {
        __syncthreads();
        #pragma unroll 4
        for (int i = 0; i < 32; i++)
            sw_s[i * D + tid] = W[(kc + i) * D + tid];
        __syncthreads();
        #pragma unroll
        for (int k = 0; k < 32; k++) {
            float4 w = *(float4*)&sw_s[k * D + c0];
            float2 w0 = make_float2(w.x, w.x);
            float2 w1 = make_float2(w.y, w.y);
            float2 w2 = make_float2(w.z, w.z);
            float2 w3 = make_float2(w.w, w.w);
            const float2* xr = (const float2*)&sxt[(kc + k) * RPAD + rg * 8];
            #pragma unroll
            for (int p = 0; p < 4; p++) {
                float2 x2 = xr[p];
                acc[p][0] = ffma2(x2, w0, acc[p][0]);
                acc[p][1] = ffma2(x2, w1, acc[p][1]);
                acc[p][2] = ffma2(x2, w2, acc[p][2]);
                acc[p][3] = ffma2(x2, w3, acc[p][3]);
            }
        }
    }

    #pragma unroll
    for (int p = 0; p < 4; p++) {
        int r0 = row0 + rg * 8 + 2 * p;
        float4 o0 = make_float4(acc[p][0].x, acc[p][1].x, acc[p][2].x, acc[p][3].x);
        float4 o1 = make_float4(acc[p][0].y, acc[p][1].y, acc[p][2].y, acc[p][3].y);
        if (r0 < N_NODES) {
            *(float4*)&g_bufB[r0 * D + c0] = o0;
            *(__half2*)&g_bufH[r0 * D + c0]     = __floats2half2_rn(o0.x * H_SCALE, o0.y * H_SCALE);
            *(__half2*)&g_bufH[r0 * D + c0 + 2] = __floats2half2_rn(o0.z * H_SCALE, o0.w * H_SCALE);
        }
        if (r0 + 1 < N_NODES) {
            *(float4*)&g_bufB[(r0 + 1) * D + c0] = o1;
            *(__half2*)&g_bufH[(r0 + 1) * D + c0]     = __floats2half2_rn(o1.x * H_SCALE, o1.y * H_SCALE);
            *(__half2*)&g_bufH[(r0 + 1) * D + c0 + 2] = __floats2half2_rn(o1.z * H_SCALE, o1.w * H_SCALE);
        }
    }
}

// ELL fill body: 8 edges per thread, 8 independent atomic->store chains.
__device__ __forceinline__ void fill_body(int fblk,
                                          const int* __restrict__ src,
                                          const int* __restrict__ dst) {
    int t = fblk * 256 + threadIdx.x;
    int e0 = t * 8;
    if (e0 >= N_EDGES) return;                  // N_EDGES % 8 == 0
    int4 dA = *(const int4*)&dst[e0];
    int4 dB = *(const int4*)&dst[e0 + 4];
    int4 sA = *(const int4*)&src[e0];
    int4 sB = *(const int4*)&src[e0 + 4];
    int p0 = atomicAdd(&g_cursor[dA.x], 1);
    int p1 = atomicAdd(&g_cursor[dA.y], 1);
    int p2 = atomicAdd(&g_cursor[dA.z], 1);
    int p3 = atomicAdd(&g_cursor[dA.w], 1);
    int p4 = atomicAdd(&g_cursor[dB.x], 1);
    int p5 = atomicAdd(&g_cursor[dB.y], 1);
    int p6 = atomicAdd(&g_cursor[dB.z], 1);
    int p7 = atomicAdd(&g_cursor[dB.w], 1);
    if (p0 < CAP) g_ell[dA.x * CAP + p0] = sA.x;
    if (p1 < CAP) g_ell[dA.y * CAP + p1] = sA.y;
    if (p2 < CAP) g_ell[dA.z * CAP + p2] = sA.z;
    if (p3 < CAP) g_ell[dA.w * CAP + p3] = sA.w;
    if (p4 < CAP) g_ell[dB.x * CAP + p4] = sB.x;
    if (p5 < CAP) g_ell[dB.y * CAP + p5] = sB.y;
    if (p6 < CAP) g_ell[dB.z * CAP + p6] = sB.z;
    if (p7 < CAP) g_ell[dB.w * CAP + p7] = sB.w;
}

// Layer-0 fused kernel: blocks [0, GEMM_GRID) do GEMM (128 active threads),
// blocks [GEMM_GRID, GEMM_GRID+FILL_GRID) do the ELL fill (256 threads).
__global__ void __launch_bounds__(256) gemm0_fill_kernel(
    const float* __restrict__ X, const float* __restrict__ W,
    const float* __restrict__ B,
    const int* __restrict__ src, const int* __restrict__ dst) {
    __shared__ float sxt[D * RPAD];
    __shared__ float sw_s[32 * D];
    if (blockIdx.x < GEMM_GRID) {
        if (threadIdx.x < 128)
            gemm_body(blockIdx.x, X, W, B, sxt, sw_s);
    } else {
        fill_body(blockIdx.x - GEMM_GRID, src, dst);
    }
}

// Layers 1..3 GEMM (reads g_bufA), 128 threads.
__global__ void __launch_bounds__(128) gemm_bias_kernel(
    const float* __restrict__ W, const float* __restrict__ B) {
    __shared__ float sxt[D * RPAD];
    __shared__ float sw_s[32 * D];
    gemm_body(blockIdx.x, g_bufA, W, B, sxt, sw_s);
}

// ---------------------------------------------------------------------------
// Aggregate + self-loop + ReLU. One warp per node. 16-edge chunks, MLP=16,
// two 8-wide HADD2 trees on pre-scaled (x 2^-6) fp16 messages folded into
// fp32. Last layer also re-zeroes g_cursor for the next launch.
// ---------------------------------------------------------------------------
__device__ __forceinline__ __half2 H2(unsigned int u) {
    return *reinterpret_cast<__half2*>(&u);
}

__device__ __forceinline__ void tree8(float4& a,
    uint2 m0, uint2 m1, uint2 m2, uint2 m3,
    uint2 m4, uint2 m5, uint2 m6, uint2 m7) {
    __half2 tL0 = __hadd2(H2(m0.x), H2(m1.x));
    __half2 tL1 = __hadd2(H2(m2.x), H2(m3.x));
    __half2 tL2 = __hadd2(H2(m4.x), H2(m5.x));
    __half2 tL3 = __hadd2(H2(m6.x), H2(m7.x));
    __half2 sL  = __hadd2(__hadd2(tL0, tL1), __hadd2(tL2, tL3));
    __half2 tH0 = __hadd2(H2(m0.y), H2(m1.y));
    __half2 tH1 = __hadd2(H2(m2.y), H2(m3.y));
    __half2 tH2 = __hadd2(H2(m4.y), H2(m5.y));
    __half2 tH3 = __hadd2(H2(m6.y), H2(m7.y));
    __half2 sH  = __hadd2(__hadd2(tH0, tH1), __hadd2(tH2, tH3));
    float2 fL = __half22float2(sL);
    float2 fH = __half22float2(sH);
    a.x = fmaf(fL.x, H_UNSCALE, a.x);
    a.y = fmaf(fL.y, H_UNSCALE, a.y);
    a.z = fmaf(fH.x, H_UNSCALE, a.z);
    a.w = fmaf(fH.y, H_UNSCALE, a.w);
}

__global__ void __launch_bounds__(256) agg_relu_kernel(float* __restrict__ ext_out,
                                                       int last_layer) {
    int gw = (blockIdx.x * blockDim.x + threadIdx.x) >> 5;
    if (gw >= N_NODES) return;
    int lane = threadIdx.x & 31;

    const float4* s4 = (const float4*)g_bufB;
    float4 a = s4[gw * 32 + lane];                 // self-loop (fp32, unscaled)

    int cnt = g_cursor[gw];
    if (last_layer && lane == 0) g_cursor[gw] = 0; // leave zeroed for next launch
    if (cnt > CAP) cnt = CAP;
    const int* el = g_ell + gw * CAP;
    const uint2* h2 = ((const uint2*)g_bufH) + lane;   // row stride = 32 uint2

    int j = 0;
    for (; j + 16 <= cnt; j += 16) {
        int4 eA = *(const int4*)&el[j];
        int4 eB = *(const int4*)&el[j + 4];
        int4 eC = *(const int4*)&el[j + 8];
        int4 eD = *(const int4*)&el[j + 12];
        uint2 m0 = h2[eA.x * 32];
        uint2 m1 = h2[eA.y * 32];
        uint2 m2 = h2[eA.z * 32];
        uint2 m3 = h2[eA.w * 32];
        uint2 m4 = h2[eB.x * 32];
        uint2 m5 = h2[eB.y * 32];
        uint2 m6 = h2[eB.z * 32];
        uint2 m7 = h2[eB.w * 32];
        uint2 n0 = h2[eC.x * 32];
        uint2 n1 = h2[eC.y * 32];
        uint2 n2 = h2[eC.z * 32];
        uint2 n3 = h2[eC.w * 32];
        uint2 n4 = h2[eD.x * 32];
        uint2 n5 = h2[eD.y * 32];
        uint2 n6 = h2[eD.z * 32];
        uint2 n7 = h2[eD.w * 32];
        tree8(a, m0, m1, m2, m3, m4, m5, m6, m7);
        tree8(a, n0, n1, n2, n3, n4, n5, n6, n7);
    }
    for (; j + 8 <= cnt; j += 8) {
        int4 eA = *(const int4*)&el[j];
        int4 eB = *(const int4*)&el[j + 4];
        uint2 m0 = h2[eA.x * 32];
        uint2 m1 = h2[eA.y * 32];
        uint2 m2 = h2[eA.z * 32];
        uint2 m3 = h2[eA.w * 32];
        uint2 m4 = h2[eB.x * 32];
        uint2 m5 = h2[eB.y * 32];
        uint2 m6 = h2[eB.z * 32];
        uint2 m7 = h2[eB.w * 32];
        tree8(a, m0, m1, m2, m3, m4, m5, m6, m7);
    }
    for (; j < cnt; j++) {
        uint2 m = h2[el[j] * 32];
        float2 fL = __half22float2(H2(m.x));
        float2 fH = __half22float2(H2(m.y));
        a.x = fmaf(fL.x, H_UNSCALE, a.x);
        a.y = fmaf(fL.y, H_UNSCALE, a.y);
        a.z = fmaf(fH.x, H_UNSCALE, a.z);
        a.w = fmaf(fH.y, H_UNSCALE, a.w);
    }

    a.x = fmaxf(a.x, 0.0f); a.y = fmaxf(a.y, 0.0f);
    a.z = fmaxf(a.z, 0.0f); a.w = fmaxf(a.w, 0.0f);
    float4* out4 = last_layer ? (float4*)ext_out : (float4*)g_bufA;
    out4[gw * 32 + lane] = a;
}

// ---------------------------------------------------------------------------
extern "C" void kernel_launch(void* const* d_in, const int* in_sizes, int n_in,
                              void* d_out, int out_size) {
    const float* node_feats = (const float*)d_in[0];
    const int*   src        = (const int*)d_in[1];
    const int*   dst        = (const int*)d_in[2];
    const float* Ws         = (const float*)d_in[3];
    const float* bs         = (const float*)d_in[4];
    float*       out        = (float*)d_out;

    int agg_grid = (N_NODES * 32 + 255) / 256;     // 1250

    // Layer 0: fused GEMM + ELL fill (cursors are zero: static init on launch 1,
    // re-zeroed by the previous launch's last agg thereafter).
    gemm0_fill_kernel<<<GEMM_GRID + FILL_GRID, 256>>>(node_feats, Ws, bs, src, dst);
    agg_relu_kernel<<<agg_grid, 256>>>(out, 0);

    for (int l = 1; l < N_LAYERS; l++) {
        gemm_bias_kernel<<<GEMM_GRID, 128>>>(Ws + (size_t)l * D * D,
                                             bs + (size_t)l * D);
        agg_relu_kernel<<<agg_grid, 256>>>(out, (l == N_LAYERS - 1) ? 1 : 0);
    }
}

// round 12
// speedup vs baseline: 1.0341x; 1.0341x over previous
#include <cuda_runtime.h>
#include <cuda_fp16.h>

#define N_NODES 10000
#define N_EDGES 640000
#define D 128
#define N_LAYERS 4
#define CAP 192            // max in-degree bucket (deg ~ Binom(640k,1e-4): mean 64, sd 8 -> 16 sigma margin)

#define H_SCALE   0.015625f   // 2^-6 applied when storing fp16 messages (exact)
#define H_UNSCALE 64.0f       // 2^6 applied when folding chunk sums into fp32

// Scratch (static __device__ — no allocations allowed; zero-initialized at load)
__device__ float  g_bufA[N_NODES * D];       // layer input (post-relu, fp32)
__device__ float  g_bufB[N_NODES * D];       // hl = X@W + b (fp32, self-loop + precision)
__device__ __half g_bufH[N_NODES * D];       // hl * 2^-6 in fp16 (gather operand)
__device__ int    g_cursor[N_NODES];         // per-node degree counter (left at 0 by every launch)
__device__ int    g_ell[N_NODES * CAP];      // padded per-dst source lists

// ---------------------------------------------------------------------------
// ELL fill: 8 edges per thread, 8 independent atomic->store chains.
// Cursors are zero on entry (static init on launch 1; last agg re-zeroes after).
// ---------------------------------------------------------------------------
__global__ void fill_ell_kernel(const int* __restrict__ src,
                                const int* __restrict__ dst) {
    int t = blockIdx.x * blockDim.x + threadIdx.x;
    int e0 = t * 8;
    if (e0 >= N_EDGES) return;                  // N_EDGES % 8 == 0
    int4 dA = *(const int4*)&dst[e0];
    int4 dB = *(const int4*)&dst[e0 + 4];
    int4 sA = *(const int4*)&src[e0];
    int4 sB = *(const int4*)&src[e0 + 4];
    int p0 = atomicAdd(&g_cursor[dA.x], 1);
    int p1 = atomicAdd(&g_cursor[dA.y], 1);
    int p2 = atomicAdd(&g_cursor[dA.z], 1);
    int p3 = atomicAdd(&g_cursor[dA.w], 1);
    int p4 = atomicAdd(&g_cursor[dB.x], 1);
    int p5 = atomicAdd(&g_cursor[dB.y], 1);
    int p6 = atomicAdd(&g_cursor[dB.z], 1);
    int p7 = atomicAdd(&g_cursor[dB.w], 1);
    if (p0 < CAP) g_ell[dA.x * CAP + p0] = sA.x;
    if (p1 < CAP) g_ell[dA.y * CAP + p1] = sA.y;
    if (p2 < CAP) g_ell[dA.z * CAP + p2] = sA.z;
    if (p3 < CAP) g_ell[dA.w * CAP + p3] = sA.w;
    if (p4 < CAP) g_ell[dB.x * CAP + p4] = sB.x;
    if (p5 < CAP) g_ell[dB.y * CAP + p5] = sB.y;
    if (p6 < CAP) g_ell[dB.z * CAP + p6] = sB.z;
    if (p7 < CAP) g_ell[dB.w * CAP + p7] = sB.w;
}

// ---------------------------------------------------------------------------
// GEMM: Y = X @ W + b using packed dual-fp32 FMA (fma.rn.f32x2).
// 32 rows x 128 cols per block, 128 threads.
// ---------------------------------------------------------------------------
#define GR 32
#define RPAD (GR + 2)

__device__ __forceinline__ float2 ffma2(float2 a, float2 b, float2 c) {
    unsigned long long ua = *reinterpret_cast<unsigned long long*>(&a);
    unsigned long long ub = *reinterpret_cast<unsigned long long*>(&b);
    unsigned long long uc = *reinterpret_cast<unsigned long long*>(&c);
    unsigned long long r;
    asm("fma.rn.f32x2 %0, %1, %2, %3;" : "=l"(r) : "l"(ua), "l"(ub), "l"(uc));
    return *reinterpret_cast<float2*>(&r);
}

__global__ void __launch_bounds__(128) gemm_bias_kernel(
    const float* __restrict__ ext_X, int use_ext,
    const float* __restrict__ W, const float* __restrict__ B) {
    __shared__ float sxt[D][RPAD];     // [k][r] transposed X tile
    __shared__ float sw_s[32][D];      // W chunk
    const float* X = use_ext ? ext_X : g_bufA;

    int tid = threadIdx.x;
    int cg = tid & 31, rg = tid >> 5;
    int c0 = cg * 4;
    int row0 = blockIdx.x * GR;

    #pragma unroll 4
    for (int r = 0; r < GR; r++) {
        int gr = row0 + r;
        sxt[tid][r] = (gr < N_NODES) ? X[gr * D + tid] : 0.0f;
    }

    float4 bias = *(const float4*)&B[c0];
    float2 acc[4][4];
    #pragma unroll
    for (int p = 0; p < 4; p++) {
        acc[p][0] = make_float2(bias.x, bias.x);
        acc[p][1] = make_float2(bias.y, bias.y);
        acc[p][2] = make_float2(bias.z, bias.z);
        acc[p][3] = make_float2(bias.w, bias.w);
    }

    for (int kc = 0; kc < D; kc += 32) {
        __syncthreads();
        #pragma unroll 4
        for (int i = 0; i < 32; i++)
            sw_s[i][tid] = W[(kc + i) * D + tid];
        __syncthreads();
        #pragma unroll
        for (int k = 0; k < 32; k++) {
            float4 w = *(float4*)&sw_s[k][c0];
            float2 w0 = make_float2(w.x, w.x);
            float2 w1 = make_float2(w.y, w.y);
            float2 w2 = make_float2(w.z, w.z);
            float2 w3 = make_float2(w.w, w.w);
            const float2* xr = (const float2*)&sxt[kc + k][rg * 8];
            #pragma unroll
            for (int p = 0; p < 4; p++) {
                float2 x2 = xr[p];
                acc[p][0] = ffma2(x2, w0, acc[p][0]);
                acc[p][1] = ffma2(x2, w1, acc[p][1]);
                acc[p][2] = ffma2(x2, w2, acc[p][2]);
                acc[p][3] = ffma2(x2, w3, acc[p][3]);
            }
        }
    }

    #pragma unroll
    for (int p = 0; p < 4; p++) {
        int r0 = row0 + rg * 8 + 2 * p;
        float4 o0 = make_float4(acc[p][0].x, acc[p][1].x, acc[p][2].x, acc[p][3].x);
        float4 o1 = make_float4(acc[p][0].y, acc[p][1].y, acc[p][2].y, acc[p][3].y);
        if (r0 < N_NODES) {
            *(float4*)&g_bufB[r0 * D + c0] = o0;
            *(__half2*)&g_bufH[r0 * D + c0]     = __floats2half2_rn(o0.x * H_SCALE, o0.y * H_SCALE);
            *(__half2*)&g_bufH[r0 * D + c0 + 2] = __floats2half2_rn(o0.z * H_SCALE, o0.w * H_SCALE);
        }
        if (r0 + 1 < N_NODES) {
            *(float4*)&g_bufB[(r0 + 1) * D + c0] = o1;
            *(__half2*)&g_bufH[(r0 + 1) * D + c0]     = __floats2half2_rn(o1.x * H_SCALE, o1.y * H_SCALE);
            *(__half2*)&g_bufH[(r0 + 1) * D + c0 + 2] = __floats2half2_rn(o1.z * H_SCALE, o1.w * H_SCALE);
        }
    }
}

// ---------------------------------------------------------------------------
// Aggregate + self-loop + ReLU. HALF-WARP (16 lanes) per node: fp16 row =
// 256B = 16 x LDG.128, so one load instruction per edge per half-warp (2x
// fewer than the 32-lane layout). 128-thread blocks -> 9 blocks/SM -> grid
// 1250 fits in ONE wave. 8-edge chunks, depth-3 scaled HADD2 trees (numerics
// identical to R8/R9). Last layer re-zeroes g_cursor for the next launch.
// ---------------------------------------------------------------------------
__device__ __forceinline__ __half2 H2(unsigned int u) {
    return *reinterpret_cast<__half2*>(&u);
}

__device__ __forceinline__ void tree8_u4(float4& a0, float4& a1,
    uint4 m0, uint4 m1, uint4 m2, uint4 m3,
    uint4 m4, uint4 m5, uint4 m6, uint4 m7) {
    __half2 sx = __hadd2(__hadd2(__hadd2(H2(m0.x), H2(m1.x)), __hadd2(H2(m2.x), H2(m3.x))),
                         __hadd2(__hadd2(H2(m4.x), H2(m5.x)), __hadd2(H2(m6.x), H2(m7.x))));
    __half2 sy = __hadd2(__hadd2(__hadd2(H2(m0.y), H2(m1.y)), __hadd2(H2(m2.y), H2(m3.y))),
                         __hadd2(__hadd2(H2(m4.y), H2(m5.y)), __hadd2(H2(m6.y), H2(m7.y))));
    __half2 sz = __hadd2(__hadd2(__hadd2(H2(m0.z), H2(m1.z)), __hadd2(H2(m2.z), H2(m3.z))),
                         __hadd2(__hadd2(H2(m4.z), H2(m5.z)), __hadd2(H2(m6.z), H2(m7.z))));
    __half2 sw = __hadd2(__hadd2(__hadd2(H2(m0.w), H2(m1.w)), __hadd2(H2(m2.w), H2(m3.w))),
                         __hadd2(__hadd2(H2(m4.w), H2(m5.w)), __hadd2(H2(m6.w), H2(m7.w))));
    float2 f;
    f = __half22float2(sx); a0.x = fmaf(f.x, H_UNSCALE, a0.x); a0.y = fmaf(f.y, H_UNSCALE, a0.y);
    f = __half22float2(sy); a0.z = fmaf(f.x, H_UNSCALE, a0.z); a0.w = fmaf(f.y, H_UNSCALE, a0.w);
    f = __half22float2(sz); a1.x = fmaf(f.x, H_UNSCALE, a1.x); a1.y = fmaf(f.y, H_UNSCALE, a1.y);
    f = __half22float2(sw); a1.z = fmaf(f.x, H_UNSCALE, a1.z); a1.w = fmaf(f.y, H_UNSCALE, a1.w);
}

__global__ void __launch_bounds__(128) agg_relu_kernel(float* __restrict__ ext_out,
                                                       int last_layer) {
    int t = blockIdx.x * 128 + threadIdx.x;
    int node = t >> 4;                 // half-warp per node
    if (node >= N_NODES) return;
    int lane = t & 15;                 // 0..15; features lane*8 .. lane*8+7

    const float4* s4 = (const float4*)g_bufB;          // row = 32 float4
    float4 a0 = s4[node * 32 + lane * 2];              // self-loop (fp32)
    float4 a1 = s4[node * 32 + lane * 2 + 1];

    int cnt = g_cursor[node];
    if (last_layer && lane == 0) g_cursor[node] = 0;   // leave zeroed for next launch
    if (cnt > CAP) cnt = CAP;
    const int* el = g_ell + node * CAP;
    const uint4* h4 = ((const uint4*)g_bufH) + lane;   // row stride = 16 uint4

    int j = 0;
    for (; j + 8 <= cnt; j += 8) {
        int4 eA = *(const int4*)&el[j];                // broadcast across half-warp
        int4 eB = *(const int4*)&el[j + 4];
        uint4 m0 = h4[eA.x * 16];
        uint4 m1 = h4[eA.y * 16];
        uint4 m2 = h4[eA.z * 16];
        uint4 m3 = h4[eA.w * 16];
        uint4 m4 = h4[eB.x * 16];
        uint4 m5 = h4[eB.y * 16];
        uint4 m6 = h4[eB.z * 16];
        uint4 m7 = h4[eB.w * 16];
        tree8_u4(a0, a1, m0, m1, m2, m3, m4, m5, m6, m7);
    }
    for (; j < cnt; j++) {
        uint4 m = h4[el[j] * 16];
        float2 f;
        f = __half22float2(H2(m.x)); a0.x = fmaf(f.x, H_UNSCALE, a0.x); a0.y = fmaf(f.y, H_UNSCALE, a0.y);
        f = __half22float2(H2(m.y)); a0.z = fmaf(f.x, H_UNSCALE, a0.z); a0.w = fmaf(f.y, H_UNSCALE, a0.w);
        f = __half22float2(H2(m.z)); a1.x = fmaf(f.x, H_UNSCALE, a1.x); a1.y = fmaf(f.y, H_UNSCALE, a1.y);
        f = __half22float2(H2(m.w)); a1.z = fmaf(f.x, H_UNSCALE, a1.z); a1.w = fmaf(f.y, H_UNSCALE, a1.w);
    }

    a0.x = fmaxf(a0.x, 0.0f); a0.y = fmaxf(a0.y, 0.0f);
    a0.z = fmaxf(a0.z, 0.0f); a0.w = fmaxf(a0.w, 0.0f);
    a1.x = fmaxf(a1.x, 0.0f); a1.y = fmaxf(a1.y, 0.0f);
    a1.z = fmaxf(a1.z, 0.0f); a1.w = fmaxf(a1.w, 0.0f);
    float4* out4 = last_layer ? (float4*)ext_out : (float4*)g_bufA;
    out4[node * 32 + lane * 2]     = a0;
    out4[node * 32 + lane * 2 + 1] = a1;
}

// ---------------------------------------------------------------------------
extern "C" void kernel_launch(void* const* d_in, const int* in_sizes, int n_in,
                              void* d_out, int out_size) {
    const float* node_feats = (const float*)d_in[0];
    const int*   src        = (const int*)d_in[1];
    const int*   dst        = (const int*)d_in[2];
    const float* Ws         = (const float*)d_in[3];
    const float* bs         = (const float*)d_in[4];
    float*       out        = (float*)d_out;

    int gemm_grid = (N_NODES + GR - 1) / GR;            // 313
    int agg_grid  = (N_NODES * 16 + 127) / 128;         // 1250 (single wave @ 9 blk/SM)

    fill_ell_kernel<<<(N_EDGES / 8 + 255) / 256, 256>>>(src, dst);

    for (int l = 0; l < N_LAYERS; l++) {
        gemm_bias_kernel<<<gemm_grid, 128>>>(node_feats, (l == 0) ? 1 : 0,
                                             Ws + (size_t)l * D * D,
                                             bs + (size_t)l * D);
        agg_relu_kernel<<<agg_grid, 128>>>(out, (l == N_LAYERS - 1) ? 1 : 0);
    }
}